// round 7
// baseline (speedup 1.0000x reference)
#include <cuda_runtime.h>
#include <math.h>

// Problem constants
#define BATCH  2
#define DIM    256      // d (channels per q/k/v)
#define OCH    768      // 3*DIM
#define NPIX   4096     // H*W
#define MSPLIT 4        // split factor for row/col partial sums

// -------- scratch (device globals; total ~25 MB — no 100MB+ statics) ------
__device__ float g_q[BATCH * NPIX * DIM];     // [b][n][d], pre-scaled by d^-0.25
__device__ float g_k[BATCH * NPIX * DIM];     // [b][m][d], pre-scaled
__device__ float g_v[BATCH * NPIX * DIM];     // [b][m][d]
__device__ float g_upart[MSPLIT * BATCH * NPIX];
__device__ float g_vpart[MSPLIT * BATCH * NPIX];
__device__ float g_u [BATCH * NPIX];
__device__ float g_vp[BATCH * NPIX];

// ================================================================
// Kernel 1: qkv = W @ x + b  (1x1 conv), write q,k,v in [b][n][d]
// with q,k pre-scaled by 0.25 (= 256^-0.25).
// grid: (NPIX/64, OCH/64, BATCH), 256 threads
// ================================================================
__global__ __launch_bounds__(256)
void qkv_kernel(const float* __restrict__ x,
                const float* __restrict__ Wm,
                const float* __restrict__ bias)
{
    __shared__ float Ws[16][64];   // [k][o]
    __shared__ float Xs[16][64];   // [k][n]

    const int b     = blockIdx.z;
    const int oBase = blockIdx.y * 64;
    const int nBase = blockIdx.x * 64;
    const int tid   = threadIdx.x;

    const int wr = tid >> 2;          // 0..63  (o row)
    const int wc = (tid & 3) * 4;     // k segment
    const int xk = tid >> 4;          // 0..15 (k row)
    const int xj = (tid & 15) * 4;    // n segment

    const int ty = tid >> 4;          // o micro rows ty*4
    const int tx = tid & 15;          // n micro cols tx*4

    float acc[4][4];
    #pragma unroll
    for (int i = 0; i < 4; i++)
        #pragma unroll
        for (int j = 0; j < 4; j++) acc[i][j] = 0.f;

    const float* xb = x + (size_t)b * DIM * NPIX;

    for (int k0 = 0; k0 < DIM; k0 += 16) {
        float4 wv = *(const float4*)(Wm + (size_t)(oBase + wr) * DIM + k0 + wc);
        float4 xv = *(const float4*)(xb + (size_t)(k0 + xk) * NPIX + nBase + xj);
        __syncthreads();
        Ws[wc + 0][wr] = wv.x;
        Ws[wc + 1][wr] = wv.y;
        Ws[wc + 2][wr] = wv.z;
        Ws[wc + 3][wr] = wv.w;
        *(float4*)&Xs[xk][xj] = xv;
        __syncthreads();
        #pragma unroll
        for (int kk = 0; kk < 16; kk++) {
            float av[4], bv[4];
            *(float4*)av = *(const float4*)&Ws[kk][ty * 4];
            *(float4*)bv = *(const float4*)&Xs[kk][tx * 4];
            #pragma unroll
            for (int i = 0; i < 4; i++)
                #pragma unroll
                for (int j = 0; j < 4; j++)
                    acc[i][j] = fmaf(av[i], bv[j], acc[i][j]);
        }
    }

    #pragma unroll
    for (int i = 0; i < 4; i++) {
        const int o = oBase + ty * 4 + i;
        const float bo = __ldg(bias + o);
        #pragma unroll
        for (int j = 0; j < 4; j++) {
            const int n = nBase + tx * 4 + j;
            float val = acc[i][j] + bo;
            if (o < DIM) {
                g_q[((size_t)b * NPIX + n) * DIM + o] = val * 0.25f;
            } else if (o < 2 * DIM) {
                g_k[((size_t)b * NPIX + n) * DIM + (o - DIM)] = val * 0.25f;
            } else {
                g_v[((size_t)b * NPIX + n) * DIM + (o - 2 * DIM)] = val;
            }
        }
    }
}

// ================================================================
// Kernel 2: row sums. Block: n-tile 128 x m-range 1024, accumulates
// Sigma_m exp(q[n].k[m]) in registers (logits ~N(0,0.1): exp safe
// without max subtraction). Partials -> g_upart.
// grid: (MSPLIT, NPIX/128, BATCH), 256 threads
// ================================================================
__global__ __launch_bounds__(256)
void usum_kernel()
{
    __shared__ float As[8][128];
    __shared__ float Bs[8][128];
    __shared__ float sred[128][17];

    const int b       = blockIdx.z;
    const int nBase   = blockIdx.y * 128;
    const int mRegion = blockIdx.x * (NPIX / MSPLIT);
    const int tid = threadIdx.x;
    const int r   = tid >> 1;
    const int seg = (tid & 1) * 4;
    const int tx  = tid & 15;
    const int ty  = tid >> 4;

    const float* qb = g_q + (size_t)b * NPIX * DIM;
    const float* kb = g_k + (size_t)b * NPIX * DIM;

    float rowsum[8];
    #pragma unroll
    for (int i = 0; i < 8; i++) rowsum[i] = 0.f;

    for (int mt = 0; mt < (NPIX / MSPLIT) / 128; mt++) {
        const int mBase = mRegion + mt * 128;
        float acc[8][8];
        #pragma unroll
        for (int i = 0; i < 8; i++)
            #pragma unroll
            for (int j = 0; j < 8; j++) acc[i][j] = 0.f;

        for (int k0 = 0; k0 < DIM; k0 += 8) {
            float4 a  = *(const float4*)(qb + (size_t)(nBase + r) * DIM + k0 + seg);
            float4 bb = *(const float4*)(kb + (size_t)(mBase + r) * DIM + k0 + seg);
            __syncthreads();
            As[seg + 0][r] = a.x;  As[seg + 1][r] = a.y;
            As[seg + 2][r] = a.z;  As[seg + 3][r] = a.w;
            Bs[seg + 0][r] = bb.x; Bs[seg + 1][r] = bb.y;
            Bs[seg + 2][r] = bb.z; Bs[seg + 3][r] = bb.w;
            __syncthreads();
            #pragma unroll
            for (int kk = 0; kk < 8; kk++) {
                float av[8], bv[8];
                *(float4*)(av)     = *(const float4*)&As[kk][ty * 8];
                *(float4*)(av + 4) = *(const float4*)&As[kk][ty * 8 + 4];
                *(float4*)(bv)     = *(const float4*)&Bs[kk][tx * 8];
                *(float4*)(bv + 4) = *(const float4*)&Bs[kk][tx * 8 + 4];
                #pragma unroll
                for (int i = 0; i < 8; i++)
                    #pragma unroll
                    for (int j = 0; j < 8; j++)
                        acc[i][j] = fmaf(av[i], bv[j], acc[i][j]);
            }
        }
        #pragma unroll
        for (int i = 0; i < 8; i++)
            #pragma unroll
            for (int j = 0; j < 8; j++)
                rowsum[i] += __expf(acc[i][j]);
    }

    #pragma unroll
    for (int i = 0; i < 8; i++) sred[ty * 8 + i][tx] = rowsum[i];
    __syncthreads();
    if (tid < 128) {
        float s = 0.f;
        #pragma unroll
        for (int t = 0; t < 16; t++) s += sred[tid][t];
        g_upart[(blockIdx.x * BATCH + b) * NPIX + nBase + tid] = s;
    }
}

// ================================================================
// Kernel 3: u[b][n] = logm - log(sum of partials)
// grid: (BATCH*NPIX/256), 256 threads
// ================================================================
__global__ __launch_bounds__(256)
void ucomb_kernel()
{
    const int idx = blockIdx.x * 256 + threadIdx.x;  // = b*NPIX + n
    float s = 0.f;
    #pragma unroll
    for (int sp = 0; sp < MSPLIT; sp++)
        s += g_upart[sp * (BATCH * NPIX) + idx];
    const float logm = logf(1.0f / (float)NPIX + 1e-8f);
    g_u[idx] = logm - logf(s);
}

// ================================================================
// Kernel 4: col sums. Block: m-tile 128 x n-range 1024, accumulates
// Sigma_n exp(q[n].k[m] + u[n]). Partials -> g_vpart.
// grid: (MSPLIT, NPIX/128, BATCH), 256 threads
// ================================================================
__global__ __launch_bounds__(256)
void vsum_kernel()
{
    __shared__ float As[8][128];
    __shared__ float Bs[8][128];
    __shared__ float sred[128][17];

    const int b       = blockIdx.z;
    const int mBase   = blockIdx.y * 128;
    const int nRegion = blockIdx.x * (NPIX / MSPLIT);
    const int tid = threadIdx.x;
    const int r   = tid >> 1;
    const int seg = (tid & 1) * 4;
    const int tx  = tid & 15;
    const int ty  = tid >> 4;

    const float* qb = g_q + (size_t)b * NPIX * DIM;
    const float* kb = g_k + (size_t)b * NPIX * DIM;
    const float* ub = g_u + b * NPIX;

    float colsum[8];
    #pragma unroll
    for (int j = 0; j < 8; j++) colsum[j] = 0.f;

    for (int nt = 0; nt < (NPIX / MSPLIT) / 128; nt++) {
        const int nBase = nRegion + nt * 128;
        float acc[8][8];
        #pragma unroll
        for (int i = 0; i < 8; i++)
            #pragma unroll
            for (int j = 0; j < 8; j++) acc[i][j] = 0.f;

        for (int k0 = 0; k0 < DIM; k0 += 8) {
            float4 a  = *(const float4*)(qb + (size_t)(nBase + r) * DIM + k0 + seg);
            float4 bb = *(const float4*)(kb + (size_t)(mBase + r) * DIM + k0 + seg);
            __syncthreads();
            As[seg + 0][r] = a.x;  As[seg + 1][r] = a.y;
            As[seg + 2][r] = a.z;  As[seg + 3][r] = a.w;
            Bs[seg + 0][r] = bb.x; Bs[seg + 1][r] = bb.y;
            Bs[seg + 2][r] = bb.z; Bs[seg + 3][r] = bb.w;
            __syncthreads();
            #pragma unroll
            for (int kk = 0; kk < 8; kk++) {
                float av[8], bv[8];
                *(float4*)(av)     = *(const float4*)&As[kk][ty * 8];
                *(float4*)(av + 4) = *(const float4*)&As[kk][ty * 8 + 4];
                *(float4*)(bv)     = *(const float4*)&Bs[kk][tx * 8];
                *(float4*)(bv + 4) = *(const float4*)&Bs[kk][tx * 8 + 4];
                #pragma unroll
                for (int i = 0; i < 8; i++)
                    #pragma unroll
                    for (int j = 0; j < 8; j++)
                        acc[i][j] = fmaf(av[i], bv[j], acc[i][j]);
            }
        }
        float uval[8];
        #pragma unroll
        for (int i = 0; i < 8; i++) uval[i] = ub[nBase + ty * 8 + i];
        #pragma unroll
        for (int i = 0; i < 8; i++)
            #pragma unroll
            for (int j = 0; j < 8; j++)
                colsum[j] += __expf(acc[i][j] + uval[i]);
    }

    #pragma unroll
    for (int j = 0; j < 8; j++) sred[tx * 8 + j][ty] = colsum[j];
    __syncthreads();
    if (tid < 128) {
        float s = 0.f;
        #pragma unroll
        for (int t = 0; t < 16; t++) s += sred[tid][t];
        g_vpart[(blockIdx.x * BATCH + b) * NPIX + mBase + tid] = s;
    }
}

// ================================================================
// Kernel 5: vp[b][m] = logm - log(sum of partials)
// ================================================================
__global__ __launch_bounds__(256)
void vcomb_kernel()
{
    const int idx = blockIdx.x * 256 + threadIdx.x;
    float s = 0.f;
    #pragma unroll
    for (int sp = 0; sp < MSPLIT; sp++)
        s += g_vpart[sp * (BATCH * NPIX) + idx];
    const float logm = logf(1.0f / (float)NPIX + 1e-8f);
    g_vp[idx] = logm - logf(s);
}

// ================================================================
// Kernel 6: out[b][d][n] = e^{u[n]} * Sigma_m e^{S[n,m]+vp[m]} v[m][d]
// Flash-style: n-tile 64 x full d=256, loop m-tiles of 128.
// Smem: Ps[64][128] (32KB) + {Qs,Ks | Vs} aliased 16KB = 48KB static.
// grid: (NPIX/64, BATCH), 256 threads
// ================================================================
__global__ __launch_bounds__(256, 1)
void out_kernel(float* __restrict__ out)
{
    __shared__ float Ps[64][128];                       // [n][m], 32 KB
    __shared__ __align__(16) char shbuf[16 * 256 * 4];  // 16 KB aliased region
    float (*Qs)[64]  = (float(*)[64])shbuf;             // [8][64]
    float (*Ks)[128] = (float(*)[128])(shbuf + 8 * 64 * 4); // [8][128]
    float4 (*Vs)[64] = (float4(*)[64])shbuf;            // [16][64] float4

    const int b     = blockIdx.y;
    const int nBase = blockIdx.x * 64;
    const int tid   = threadIdx.x;
    const int tx    = tid & 15;
    const int ty    = tid >> 4;

    const float* qb  = g_q  + (size_t)b * NPIX * DIM;
    const float* kb  = g_k  + (size_t)b * NPIX * DIM;
    const float* vb  = g_v  + (size_t)b * NPIX * DIM;
    const float* vpb = g_vp + b * NPIX;

    float acc2[4][16];
    #pragma unroll
    for (int i = 0; i < 4; i++)
        #pragma unroll
        for (int j = 0; j < 16; j++) acc2[i][j] = 0.f;

    for (int mt = 0; mt < NPIX / 128; mt++) {
        const int mBase = mt * 128;

        // ---- S phase: Sacc[4n][8m] = q @ k^T for this m-tile ----
        float Sacc[4][8];
        #pragma unroll
        for (int i = 0; i < 4; i++)
            #pragma unroll
            for (int j = 0; j < 8; j++) Sacc[i][j] = 0.f;

        for (int k0 = 0; k0 < DIM; k0 += 8) {
            float4 qv, kv;
            const int lr = tid >> 1, lseg = (tid & 1) * 4;
            if (tid < 128)
                qv = *(const float4*)(qb + (size_t)(nBase + lr) * DIM + k0 + lseg);
            kv = *(const float4*)(kb + (size_t)(mBase + lr) * DIM + k0 + lseg);
            __syncthreads();
            if (tid < 128) {
                Qs[lseg + 0][lr] = qv.x; Qs[lseg + 1][lr] = qv.y;
                Qs[lseg + 2][lr] = qv.z; Qs[lseg + 3][lr] = qv.w;
            }
            Ks[lseg + 0][lr] = kv.x; Ks[lseg + 1][lr] = kv.y;
            Ks[lseg + 2][lr] = kv.z; Ks[lseg + 3][lr] = kv.w;
            __syncthreads();
            #pragma unroll
            for (int kk = 0; kk < 8; kk++) {
                float av[4], bv[8];
                *(float4*)av       = *(const float4*)&Qs[kk][ty * 4];
                *(float4*)(bv)     = *(const float4*)&Ks[kk][tx * 8];
                *(float4*)(bv + 4) = *(const float4*)&Ks[kk][tx * 8 + 4];
                #pragma unroll
                for (int i = 0; i < 4; i++)
                    #pragma unroll
                    for (int j = 0; j < 8; j++)
                        Sacc[i][j] = fmaf(av[i], bv[j], Sacc[i][j]);
            }
        }

        // ---- P = exp(S + vp[m]) into Ps[n][m] ----
        float vpv[8];
        #pragma unroll
        for (int j = 0; j < 8; j++) vpv[j] = vpb[mBase + tx * 8 + j];
        #pragma unroll
        for (int i = 0; i < 4; i++) {
            float4 p0, p1;
            p0.x = __expf(Sacc[i][0] + vpv[0]);
            p0.y = __expf(Sacc[i][1] + vpv[1]);
            p0.z = __expf(Sacc[i][2] + vpv[2]);
            p0.w = __expf(Sacc[i][3] + vpv[3]);
            p1.x = __expf(Sacc[i][4] + vpv[4]);
            p1.y = __expf(Sacc[i][5] + vpv[5]);
            p1.z = __expf(Sacc[i][6] + vpv[6]);
            p1.w = __expf(Sacc[i][7] + vpv[7]);
            *(float4*)&Ps[ty * 4 + i][tx * 8]     = p0;
            *(float4*)&Ps[ty * 4 + i][tx * 8 + 4] = p1;
        }

        // ---- PV phase: acc2 += P @ V, V staged 16 rows per step ----
        for (int sub = 0; sub < 8; sub++) {
            const int mrow = tid >> 4;     // 0..15
            float4 vl[4];
            #pragma unroll
            for (int c4 = 0; c4 < 4; c4++)
                vl[c4] = *(const float4*)(vb + (size_t)(mBase + sub * 16 + mrow) * DIM
                                          + tx * 16 + c4 * 4);
            __syncthreads();   // guards Ps writes (sub 0) / prior Vs reads
            #pragma unroll
            for (int c4 = 0; c4 < 4; c4++) Vs[mrow][tx * 4 + c4] = vl[c4];
            __syncthreads();
            #pragma unroll
            for (int kk = 0; kk < 16; kk++) {
                const int kg = (sub << 4) + kk;
                float av[4];
                #pragma unroll
                for (int i = 0; i < 4; i++) av[i] = Ps[ty * 4 + i][kg];
                #pragma unroll
                for (int jd4 = 0; jd4 < 4; jd4++) {
                    float4 v4 = Vs[kk][jd4 * 16 + tx];
                    #pragma unroll
                    for (int i = 0; i < 4; i++) {
                        acc2[i][jd4 * 4 + 0] = fmaf(av[i], v4.x, acc2[i][jd4 * 4 + 0]);
                        acc2[i][jd4 * 4 + 1] = fmaf(av[i], v4.y, acc2[i][jd4 * 4 + 1]);
                        acc2[i][jd4 * 4 + 2] = fmaf(av[i], v4.z, acc2[i][jd4 * 4 + 2]);
                        acc2[i][jd4 * 4 + 3] = fmaf(av[i], v4.w, acc2[i][jd4 * 4 + 3]);
                    }
                }
            }
        }
    }

    // ---- epilogue: scale by e^{u[n]}, store out[b][d][n] (float4 over n) ----
    float eu[4];
    #pragma unroll
    for (int i = 0; i < 4; i++)
        eu[i] = __expf(g_u[b * NPIX + nBase + ty * 4 + i]);

    #pragma unroll
    for (int jd4 = 0; jd4 < 4; jd4++) {
        #pragma unroll
        for (int c = 0; c < 4; c++) {
            const int d = jd4 * 64 + tx * 4 + c;
            float4 o;
            o.x = eu[0] * acc2[0][jd4 * 4 + c];
            o.y = eu[1] * acc2[1][jd4 * 4 + c];
            o.z = eu[2] * acc2[2][jd4 * 4 + c];
            o.w = eu[3] * acc2[3][jd4 * 4 + c];
            *(float4*)(out + ((size_t)b * DIM + d) * NPIX + nBase + ty * 4) = o;
        }
    }
}

// ================================================================
extern "C" void kernel_launch(void* const* d_in, const int* in_sizes, int n_in,
                              void* d_out, int out_size)
{
    const float* x    = (const float*)d_in[0];   // [2,256,64,64]
    const float* Wm   = (const float*)d_in[1];   // [768,256]
    const float* bias = (const float*)d_in[2];   // [768]
    float* out = (float*)d_out;                  // [2,256,64,64]

    (void)in_sizes; (void)n_in; (void)out_size;

    {   // 1) QKV projection
        dim3 g(NPIX / 64, OCH / 64, BATCH);
        qkv_kernel<<<g, 256>>>(x, Wm, bias);
    }
    {   // 2) row sums (partial)
        dim3 g(MSPLIT, NPIX / 128, BATCH);
        usum_kernel<<<g, 256>>>();
    }
    {   // 3) combine -> u
        ucomb_kernel<<<(BATCH * NPIX) / 256, 256>>>();
    }
    {   // 4) col sums (partial)
        dim3 g(MSPLIT, NPIX / 128, BATCH);
        vsum_kernel<<<g, 256>>>();
    }
    {   // 5) combine -> vp
        vcomb_kernel<<<(BATCH * NPIX) / 256, 256>>>();
    }
    {   // 6) fused S-recompute + PV -> out
        dim3 g(NPIX / 64, BATCH);
        out_kernel<<<g, 256>>>(out);
    }
}

// round 11
// speedup vs baseline: 3.2961x; 3.2961x over previous
#include <cuda_runtime.h>
#include <cuda_bf16.h>
#include <math.h>
#include <stdint.h>

// Problem constants
#define BATCH 2
#define DIM   256
#define OCH   768
#define NPIX  4096
#define MSPLIT 8
#define NT    512

// ---- arch-specific feature gate: tcgen05 only exists on sm_103a ----
#if defined(__CUDA_ARCH__) && (defined(__CUDA_ARCH_FEAT_SM103_ALL) || \
    (defined(__CUDA_ARCH_SPECIFIC__) && (__CUDA_ARCH_SPECIFIC__ == 1030)))
#define TC_OK 1
#else
#define TC_OK 0
#endif

// ---------------- scratch (~34 MB of device globals) ----------------
__device__ __nv_bfloat16 g_qh[BATCH * NPIX * DIM];   // [b][n][d] hi
__device__ __nv_bfloat16 g_ql[BATCH * NPIX * DIM];   // [b][n][d] lo
__device__ __nv_bfloat16 g_kh[BATCH * NPIX * DIM];   // [b][m][d] hi
__device__ __nv_bfloat16 g_kl[BATCH * NPIX * DIM];   // [b][m][d] lo
__device__ __nv_bfloat16 g_vth[BATCH * DIM * NPIX];  // [b][d][m] hi (tensor path B operand)
__device__ __nv_bfloat16 g_vtl[BATCH * DIM * NPIX];  // [b][d][m] lo
__device__ float g_v[BATCH * NPIX * DIM];            // [b][m][d] fp32 (fallback PV)
__device__ float g_upart[MSPLIT * BATCH * NPIX];
__device__ float g_vpart[MSPLIT * BATCH * NPIX];
__device__ float g_u [BATCH * NPIX];
__device__ float g_vp[BATCH * NPIX];

// ---------------- smem layout (dynamic, tensor kernels) ----------------
#define SM_TM   0
#define SM_MB   8
#define SM_AH   1024
#define SM_AL   (1024 + 16384)
#define SM_BH   (1024 + 32768)
#define SM_BL   (1024 + 49152)
#define SM_END  (1024 + 65536)          /* 66560 */
#define SM_RED  SM_END                  /* usum/vsum: 2 KB  */
#define SM_P0H  SM_END                  /* out: P tiles 4x16KB */
#define SM_P0L  (SM_END + 16384)
#define SM_P1H  (SM_END + 32768)
#define SM_P1L  (SM_END + 49152)
#define SMEM_SUM (SM_END + 2048)        /* 68608  */
#define SMEM_OUT (SM_END + 65536)       /* 132096 */

// idesc: kind::f16, dtype=F32, atype=btype=BF16, M=128, N=128
#define IDESC 0x8200490u

#define SW128(x) ((x) ^ (((x) >> 3) & 0x70))

// ---------------- shared helpers ----------------
__device__ __forceinline__ float4 ld_split4(const __nv_bfloat16* __restrict__ h,
                                            const __nv_bfloat16* __restrict__ l,
                                            size_t idx) {
    float2 h01 = __bfloat1622float2(*(const __nv_bfloat162*)(h + idx));
    float2 h23 = __bfloat1622float2(*(const __nv_bfloat162*)(h + idx + 2));
    float2 l01 = __bfloat1622float2(*(const __nv_bfloat162*)(l + idx));
    float2 l23 = __bfloat1622float2(*(const __nv_bfloat162*)(l + idx + 2));
    return make_float4(h01.x + l01.x, h01.y + l01.y, h23.x + l23.x, h23.y + l23.y);
}

#if TC_OK
// ---------------- PTX helpers (sm_103a only) ----------------
__device__ __forceinline__ uint32_t smem_u32(const void* p) {
    uint32_t a;
    asm("{ .reg .u64 t; cvta.to.shared.u64 t, %1; cvt.u32.u64 %0, t; }" : "=r"(a) : "l"(p));
    return a;
}
__device__ __forceinline__ bool elect1() {
    uint32_t p;
    asm volatile("{\n\t.reg .pred p;\n\telect.sync _|p, 0xFFFFFFFF;\n\t"
                 "selp.b32 %0, 1, 0, p;\n\t}" : "=r"(p));
    return p != 0;
}
__device__ __forceinline__ uint64_t mkdesc(uint32_t a) {
    const uint64_t base = (2ull << 61) | (1ull << 46) | (64ull << 32) | (1ull << 16);
    return base | ((uint64_t)(a >> 4) & 0x3FFF);
}
#define TC_ALLOC(smaddr, n) \
    asm volatile("tcgen05.alloc.cta_group::1.sync.aligned.shared::cta.b32 [%0], %1;" \
                 :: "r"((uint32_t)(smaddr)), "r"((uint32_t)(n)) : "memory")
#define TC_DEALLOC(tm, n) \
    asm volatile("tcgen05.dealloc.cta_group::1.sync.aligned.b32 %0, %1;" :: "r"(tm), "r"((uint32_t)(n)))
#define TC_COMMIT(mb) \
    asm volatile("tcgen05.commit.cta_group::1.mbarrier::arrive::one.shared::cluster.b64 [%0];" \
                 :: "r"((uint32_t)(mb)) : "memory")
#define TC_WAIT_LD()  asm volatile("tcgen05.wait::ld.sync.aligned;" ::: "memory")
#define TC_FENCE_BEFORE() asm volatile("tcgen05.fence::before_thread_sync;" ::: "memory")
#define TC_FENCE_AFTER()  asm volatile("tcgen05.fence::after_thread_sync;" ::: "memory")
#define FENCE_ASYNC() asm volatile("fence.proxy.async.shared::cta;" ::: "memory")
#define MB_INIT(mb, cnt) \
    asm volatile("mbarrier.init.shared.b64 [%0], %1;" :: "r"((uint32_t)(mb)), "r"((uint32_t)(cnt)) : "memory")
#define MB_INVAL(mb) \
    asm volatile("mbarrier.inval.shared.b64 [%0];" :: "r"((uint32_t)(mb)) : "memory")

#define MB_WAIT_PARITY(mbaddr, par) do {                                        \
    uint32_t _mb = (uint32_t)(mbaddr); uint32_t _pa = (uint32_t)(par);          \
    uint32_t _done;                                                             \
    asm volatile("{\n\t.reg .pred p;\n\t"                                       \
        "mbarrier.try_wait.parity.acquire.cta.shared::cta.b64 p, [%1], %2;\n\t" \
        "selp.b32 %0, 1, 0, p;\n\t}" : "=r"(_done) : "r"(_mb), "r"(_pa) : "memory"); \
    if (!_done) {                                                               \
        asm volatile("{\n\t.reg .pred P1;\n\t"                                  \
            "WL_%=:\n\t"                                                        \
            "mbarrier.try_wait.parity.acquire.cta.shared::cta.b64 P1, [%0], %1, 0x989680;\n\t" \
            "@P1 bra.uni WD_%=;\n\t"                                            \
            "bra.uni WL_%=;\n\t"                                                \
            "WD_%=:\n\t}" :: "r"(_mb), "r"(_pa) : "memory");                    \
    }                                                                           \
} while (0)

#define LDTM_X32(r, addr)                                                       \
    asm volatile("tcgen05.ld.sync.aligned.32x32b.x32.b32 "                      \
        "{%0, %1, %2, %3, %4, %5, %6, %7, "                                     \
        " %8, %9, %10, %11, %12, %13, %14, %15, "                               \
        " %16, %17, %18, %19, %20, %21, %22, %23, "                             \
        " %24, %25, %26, %27, %28, %29, %30, %31}, [%32];"                      \
        : "=r"((r)[0]),  "=r"((r)[1]),  "=r"((r)[2]),  "=r"((r)[3]),            \
          "=r"((r)[4]),  "=r"((r)[5]),  "=r"((r)[6]),  "=r"((r)[7]),            \
          "=r"((r)[8]),  "=r"((r)[9]),  "=r"((r)[10]), "=r"((r)[11]),           \
          "=r"((r)[12]), "=r"((r)[13]), "=r"((r)[14]), "=r"((r)[15]),           \
          "=r"((r)[16]), "=r"((r)[17]), "=r"((r)[18]), "=r"((r)[19]),           \
          "=r"((r)[20]), "=r"((r)[21]), "=r"((r)[22]), "=r"((r)[23]),           \
          "=r"((r)[24]), "=r"((r)[25]), "=r"((r)[26]), "=r"((r)[27]),           \
          "=r"((r)[28]), "=r"((r)[29]), "=r"((r)[30]), "=r"((r)[31])            \
        : "r"(addr))

__device__ __forceinline__ void mma_f16_ss(uint32_t d, uint64_t a, uint64_t b, uint32_t en) {
    asm volatile(
        "{\n\t.reg .pred p;\n\tsetp.ne.u32 p, %5, 0;\n\t"
        "tcgen05.mma.cta_group::1.kind::f16 [%0], %1, %2, %3, {%4, %4, %4, %4}, p;\n\t}"
        :: "r"(d), "l"(a), "l"(b), "r"(IDESC), "r"(0u), "r"(en) : "memory");
}

// 12 MMAs: (Ah,Bh),(Al,Bh),(Ah,Bl) over 4 K-steps of 16 bf16 (32B = 2 desc units)
__device__ __forceinline__ void mma3(uint32_t dtm, uint32_t ah, uint32_t al,
                                     uint32_t bh, uint32_t bl, bool& first) {
    uint64_t dah = mkdesc(ah), dal = mkdesc(al), dbh = mkdesc(bh), dbl = mkdesc(bl);
    #pragma unroll
    for (int j = 0; j < 4; j++) {
        mma_f16_ss(dtm, dah + j * 2, dbh + j * 2, first ? 0u : 1u); first = false;
        mma_f16_ss(dtm, dal + j * 2, dbh + j * 2, 1u);
        mma_f16_ss(dtm, dah + j * 2, dbl + j * 2, 1u);
    }
}

// stage a [128 rows][64 bf16] tile (128B rows, SW128) from gmem
__device__ __forceinline__ void stage64(char* dst, const __nv_bfloat16* __restrict__ src,
                                        int rowBase, int srcStride, int colBase, int tid) {
    #pragma unroll
    for (int s = tid; s < 1024; s += NT) {
        int row = s >> 3, seg = s & 7;
        uint4 v = *(const uint4*)(src + (size_t)(rowBase + row) * srcStride + colBase + seg * 8);
        *(uint4*)(dst + SW128(row * 128 + seg * 16)) = v;
    }
}

struct Sync { int pending; int parity; };
__device__ __forceinline__ void waitIf(uint32_t mb, Sync& s) {
    if (s.pending) { MB_WAIT_PARITY(mb, s.parity); s.parity ^= 1; s.pending = 0; }
}

// Compute S tile [128 n][128 m] into TMEM cols 0..127 (split bf16, fp32 accum).
__device__ __forceinline__ void s_tile(char* sm, uint32_t smb, uint32_t tmem,
                                       const __nv_bfloat16* qh, const __nv_bfloat16* ql,
                                       const __nv_bfloat16* kh, const __nv_bfloat16* kl,
                                       int nBase, int mBase, int tid, Sync& sy) {
    bool first = true;
    for (int kc = 0; kc < 4; kc++) {
        waitIf(smb + SM_MB, sy);
        __syncthreads();
        stage64(sm + SM_AH, qh, nBase, DIM, kc * 64, tid);
        stage64(sm + SM_AL, ql, nBase, DIM, kc * 64, tid);
        stage64(sm + SM_BH, kh, mBase, DIM, kc * 64, tid);
        stage64(sm + SM_BL, kl, mBase, DIM, kc * 64, tid);
        FENCE_ASYNC();
        __syncthreads();
        if (tid < 32 && elect1()) {
            mma3(tmem, smb + SM_AH, smb + SM_AL, smb + SM_BH, smb + SM_BL, first);
            TC_COMMIT(smb + SM_MB);
        }
        sy.pending = 1;
    }
    waitIf(smb + SM_MB, sy);
    TC_FENCE_AFTER();
}
#endif  // TC_OK

// ================================================================
// Kernel 1 (shared): qkv = W@x + b; writes bf16 splits (tensor path)
// AND fp32 g_v (fallback PV path).
// ================================================================
__global__ __launch_bounds__(256)
void qkv_kernel(const float* __restrict__ x,
                const float* __restrict__ Wm,
                const float* __restrict__ bias)
{
    __shared__ float Ws[16][64];
    __shared__ float Xs[16][64];

    const int b     = blockIdx.z;
    const int oBase = blockIdx.y * 64;
    const int nBase = blockIdx.x * 64;
    const int tid   = threadIdx.x;

    const int wr = tid >> 2, wc = (tid & 3) * 4;
    const int xk = tid >> 4, xj = (tid & 15) * 4;
    const int ty = tid >> 4, tx = tid & 15;

    float acc[4][4];
    #pragma unroll
    for (int i = 0; i < 4; i++)
        #pragma unroll
        for (int j = 0; j < 4; j++) acc[i][j] = 0.f;

    const float* xb = x + (size_t)b * DIM * NPIX;

    for (int k0 = 0; k0 < DIM; k0 += 16) {
        float4 wv = *(const float4*)(Wm + (size_t)(oBase + wr) * DIM + k0 + wc);
        float4 xv = *(const float4*)(xb + (size_t)(k0 + xk) * NPIX + nBase + xj);
        __syncthreads();
        Ws[wc + 0][wr] = wv.x; Ws[wc + 1][wr] = wv.y;
        Ws[wc + 2][wr] = wv.z; Ws[wc + 3][wr] = wv.w;
        *(float4*)&Xs[xk][xj] = xv;
        __syncthreads();
        #pragma unroll
        for (int kk = 0; kk < 16; kk++) {
            float av[4], bv[4];
            *(float4*)av = *(const float4*)&Ws[kk][ty * 4];
            *(float4*)bv = *(const float4*)&Xs[kk][tx * 4];
            #pragma unroll
            for (int i = 0; i < 4; i++)
                #pragma unroll
                for (int j = 0; j < 4; j++)
                    acc[i][j] = fmaf(av[i], bv[j], acc[i][j]);
        }
    }

    #pragma unroll
    for (int i = 0; i < 4; i++) {
        const int o = oBase + ty * 4 + i;
        const float bo = __ldg(bias + o);
        #pragma unroll
        for (int j = 0; j < 4; j++) {
            const int n = nBase + tx * 4 + j;
            float val = acc[i][j] + bo;
            if (o < DIM) {
                float sv = val * 0.25f;
                __nv_bfloat16 h = __float2bfloat16(sv);
                __nv_bfloat16 l = __float2bfloat16(sv - __bfloat162float(h));
                size_t idx = ((size_t)b * NPIX + n) * DIM + o;
                g_qh[idx] = h; g_ql[idx] = l;
            } else if (o < 2 * DIM) {
                float sv = val * 0.25f;
                __nv_bfloat16 h = __float2bfloat16(sv);
                __nv_bfloat16 l = __float2bfloat16(sv - __bfloat162float(h));
                size_t idx = ((size_t)b * NPIX + n) * DIM + (o - DIM);
                g_kh[idx] = h; g_kl[idx] = l;
            } else {
                const int d = o - 2 * DIM;
                __nv_bfloat16 h = __float2bfloat16(val);
                __nv_bfloat16 l = __float2bfloat16(val - __bfloat162float(h));
                size_t idxT = ((size_t)b * DIM + d) * NPIX + n;
                g_vth[idxT] = h; g_vtl[idxT] = l;
                g_v[((size_t)b * NPIX + n) * DIM + d] = val;
            }
        }
    }
}

// ================================================================
// Tensor-path kernels (bodies only on sm_103a; stubs elsewhere)
// ================================================================
__global__ __launch_bounds__(NT)
void usum_t()
{
#if TC_OK
    extern __shared__ char sm[];
    uint32_t smb = smem_u32(sm);
    const int tid = threadIdx.x, w = tid >> 5, lane = tid & 31;
    const int g = w >> 2, sub = w & 3, row = sub * 32 + lane;
    const int b = blockIdx.z, nBase = blockIdx.y * 128, region = blockIdx.x;

    if (w == 0) TC_ALLOC(smb + SM_TM, 512);
    if (tid == 0) MB_INIT(smb + SM_MB, 1);
    __syncthreads();
    uint32_t tmem;
    asm volatile("ld.shared.b32 %0, [%1];" : "=r"(tmem) : "r"(smb + SM_TM));

    const __nv_bfloat16* qh = g_qh + (size_t)b * NPIX * DIM;
    const __nv_bfloat16* ql = g_ql + (size_t)b * NPIX * DIM;
    const __nv_bfloat16* kh = g_kh + (size_t)b * NPIX * DIM;
    const __nv_bfloat16* kl = g_kl + (size_t)b * NPIX * DIM;

    Sync sy = {0, 0};
    float rs = 0.f;
    for (int mt = 0; mt < NPIX / MSPLIT / 128; mt++) {
        const int mBase = region * (NPIX / MSPLIT) + mt * 128;
        s_tile(sm, smb, tmem, qh, ql, kh, kl, nBase, mBase, tid, sy);
        uint32_t r[32];
        LDTM_X32(r, tmem + g * 32);
        TC_WAIT_LD();
        TC_FENCE_BEFORE();
        #pragma unroll
        for (int c = 0; c < 32; c++) rs += __expf(__uint_as_float(r[c]));
    }
    __syncthreads();
    float* red = (float*)(sm + SM_RED);
    red[row * 4 + g] = rs;
    __syncthreads();
    if (tid < 128) {
        float s = red[tid * 4] + red[tid * 4 + 1] + red[tid * 4 + 2] + red[tid * 4 + 3];
        g_upart[((size_t)region * BATCH + b) * NPIX + nBase + tid] = s;
    }
    __syncthreads();
    if (tid == 0) MB_INVAL(smb + SM_MB);
    __syncthreads();
    if (w == 0) TC_DEALLOC(tmem, 512);
#endif
}

__global__ __launch_bounds__(NT)
void vsum_t()
{
#if TC_OK
    extern __shared__ char sm[];
    uint32_t smb = smem_u32(sm);
    const int tid = threadIdx.x, w = tid >> 5, lane = tid & 31;
    const int g = w >> 2, sub = w & 3, row = sub * 32 + lane;
    const int b = blockIdx.z, mBase = blockIdx.y * 128, region = blockIdx.x;

    if (w == 0) TC_ALLOC(smb + SM_TM, 512);
    if (tid == 0) MB_INIT(smb + SM_MB, 1);
    __syncthreads();
    uint32_t tmem;
    asm volatile("ld.shared.b32 %0, [%1];" : "=r"(tmem) : "r"(smb + SM_TM));

    const __nv_bfloat16* qh = g_qh + (size_t)b * NPIX * DIM;
    const __nv_bfloat16* ql = g_ql + (size_t)b * NPIX * DIM;
    const __nv_bfloat16* kh = g_kh + (size_t)b * NPIX * DIM;
    const __nv_bfloat16* kl = g_kl + (size_t)b * NPIX * DIM;

    Sync sy = {0, 0};
    float cacc[32];
    #pragma unroll
    for (int c = 0; c < 32; c++) cacc[c] = 0.f;

    for (int nt = 0; nt < NPIX / MSPLIT / 128; nt++) {
        const int nBase = region * (NPIX / MSPLIT) + nt * 128;
        s_tile(sm, smb, tmem, qh, ql, kh, kl, nBase, mBase, tid, sy);
        uint32_t r[32];
        LDTM_X32(r, tmem + g * 32);
        TC_WAIT_LD();
        TC_FENCE_BEFORE();
        const float ur = g_u[b * NPIX + nBase + row];
        #pragma unroll
        for (int c = 0; c < 32; c++) {
            float xv = __expf(__uint_as_float(r[c]) + ur);
            #pragma unroll
            for (int st = 16; st > 0; st >>= 1)
                xv += __shfl_xor_sync(0xFFFFFFFFu, xv, st);
            cacc[c] += xv;
        }
    }
    __syncthreads();
    float* red = (float*)(sm + SM_RED);
    if (lane == 0) {
        #pragma unroll
        for (int c = 0; c < 32; c++) red[(g * 32 + c) * 4 + sub] = cacc[c];
    }
    __syncthreads();
    if (tid < 128) {
        float s = red[tid * 4] + red[tid * 4 + 1] + red[tid * 4 + 2] + red[tid * 4 + 3];
        g_vpart[((size_t)region * BATCH + b) * NPIX + mBase + tid] = s;
    }
    __syncthreads();
    if (tid == 0) MB_INVAL(smb + SM_MB);
    __syncthreads();
    if (w == 0) TC_DEALLOC(tmem, 512);
#endif
}

__global__ __launch_bounds__(NT)
void out_t(float* __restrict__ out)
{
#if TC_OK
    extern __shared__ char sm[];
    uint32_t smb = smem_u32(sm);
    const int tid = threadIdx.x, w = tid >> 5, lane = tid & 31;
    const int g = w >> 2, sub = w & 3, row = sub * 32 + lane;
    const int b = blockIdx.y, nBase = blockIdx.x * 128;

    if (w == 0) TC_ALLOC(smb + SM_TM, 512);
    if (tid == 0) MB_INIT(smb + SM_MB, 1);
    __syncthreads();
    uint32_t tmem;
    asm volatile("ld.shared.b32 %0, [%1];" : "=r"(tmem) : "r"(smb + SM_TM));

    const __nv_bfloat16* qh  = g_qh  + (size_t)b * NPIX * DIM;
    const __nv_bfloat16* ql  = g_ql  + (size_t)b * NPIX * DIM;
    const __nv_bfloat16* kh  = g_kh  + (size_t)b * NPIX * DIM;
    const __nv_bfloat16* kl  = g_kl  + (size_t)b * NPIX * DIM;
    const __nv_bfloat16* vth = g_vth + (size_t)b * DIM * NPIX;
    const __nv_bfloat16* vtl = g_vtl + (size_t)b * DIM * NPIX;

    Sync sy = {0, 0};
    bool pvF0 = true, pvF1 = true;

    for (int mt = 0; mt < NPIX / 128; mt++) {
        const int mBase = mt * 128;
        s_tile(sm, smb, tmem, qh, ql, kh, kl, nBase, mBase, tid, sy);

        uint32_t r[32];
        LDTM_X32(r, tmem + g * 32);
        TC_WAIT_LD();
        TC_FENCE_BEFORE();
        char* pH = sm + ((g >> 1) ? SM_P1H : SM_P0H);
        char* pL = sm + ((g >> 1) ? SM_P1L : SM_P0L);
        #pragma unroll
        for (int c = 0; c < 32; c++) {
            float vpc = g_vp[b * NPIX + mBase + g * 32 + c];
            float p = __expf(__uint_as_float(r[c]) + vpc);
            __nv_bfloat16 h = __float2bfloat16(p);
            __nv_bfloat16 l = __float2bfloat16(p - __bfloat162float(h));
            uint32_t off = SW128((uint32_t)(row * 128 + ((g & 1) * 32 + c) * 2));
            *(__nv_bfloat16*)(pH + off) = h;
            *(__nv_bfloat16*)(pL + off) = l;
        }
        FENCE_ASYNC();

        for (int dh = 0; dh < 2; dh++) {
            for (int c2 = 0; c2 < 2; c2++) {
                waitIf(smb + SM_MB, sy);
                __syncthreads();
                stage64(sm + SM_BH, vth, dh * 128, NPIX, mBase + c2 * 64, tid);
                stage64(sm + SM_BL, vtl, dh * 128, NPIX, mBase + c2 * 64, tid);
                FENCE_ASYNC();
                __syncthreads();
                if (tid < 32 && elect1()) {
                    bool& f = dh ? pvF1 : pvF0;
                    mma3(tmem + 128 + dh * 128,
                         smb + (c2 ? SM_P1H : SM_P0H), smb + (c2 ? SM_P1L : SM_P0L),
                         smb + SM_BH, smb + SM_BL, f);
                    TC_COMMIT(smb + SM_MB);
                }
                sy.pending = 1;
            }
        }
    }

    waitIf(smb + SM_MB, sy);
    TC_FENCE_AFTER();

    uint32_t r0[32], r1[32];
    LDTM_X32(r0, tmem + 128 + g * 64);
    LDTM_X32(r1, tmem + 128 + g * 64 + 32);
    TC_WAIT_LD();
    TC_FENCE_BEFORE();
    const float eu = __expf(g_u[b * NPIX + nBase + row]);

    float* T = (float*)(sm + SM_P0H);   // [64][132]
    for (int rnd = 0; rnd < 4; rnd++) {
        __syncthreads();
        if (g == rnd) {
            #pragma unroll
            for (int c = 0; c < 32; c++) T[c * 132 + row] = __uint_as_float(r0[c]) * eu;
            #pragma unroll
            for (int c = 0; c < 32; c++) T[(32 + c) * 132 + row] = __uint_as_float(r1[c]) * eu;
        }
        __syncthreads();
        const int dl = tid >> 3, ns = (tid & 7) * 16;
        float* dst = out + ((size_t)(b * DIM + rnd * 64 + dl)) * NPIX + nBase + ns;
        const float* src = T + dl * 132 + ns;
        #pragma unroll
        for (int i = 0; i < 4; i++)
            *(float4*)(dst + i * 4) = *(const float4*)(src + i * 4);
    }

    __syncthreads();
    if (tid == 0) MB_INVAL(smb + SM_MB);
    __syncthreads();
    if (w == 0) TC_DEALLOC(tmem, 512);
#else
    (void)out;
#endif
}

// ================================================================
// FFMA fallback kernels (R7-proven bodies; stubs on sm_103a).
// q/k reconstructed as hi+lo fp32 from the bf16 splits.
// ================================================================
__global__ __launch_bounds__(256)
void usum_f()
{
#if !TC_OK
    __shared__ float As[8][128];
    __shared__ float Bs[8][128];
    __shared__ float sred[128][17];

    const int b       = blockIdx.z;
    const int nBase   = blockIdx.y * 128;
    const int mRegion = blockIdx.x * (NPIX / MSPLIT);
    const int tid = threadIdx.x;
    const int r   = tid >> 1;
    const int seg = (tid & 1) * 4;
    const int tx  = tid & 15;
    const int ty  = tid >> 4;

    const __nv_bfloat16* qh = g_qh + (size_t)b * NPIX * DIM;
    const __nv_bfloat16* ql = g_ql + (size_t)b * NPIX * DIM;
    const __nv_bfloat16* kh = g_kh + (size_t)b * NPIX * DIM;
    const __nv_bfloat16* kl = g_kl + (size_t)b * NPIX * DIM;

    float rowsum[8];
    #pragma unroll
    for (int i = 0; i < 8; i++) rowsum[i] = 0.f;

    for (int mt = 0; mt < (NPIX / MSPLIT) / 128; mt++) {
        const int mBase = mRegion + mt * 128;
        float acc[8][8];
        #pragma unroll
        for (int i = 0; i < 8; i++)
            #pragma unroll
            for (int j = 0; j < 8; j++) acc[i][j] = 0.f;

        for (int k0 = 0; k0 < DIM; k0 += 8) {
            float4 a  = ld_split4(qh, ql, (size_t)(nBase + r) * DIM + k0 + seg);
            float4 bb = ld_split4(kh, kl, (size_t)(mBase + r) * DIM + k0 + seg);
            __syncthreads();
            As[seg + 0][r] = a.x;  As[seg + 1][r] = a.y;
            As[seg + 2][r] = a.z;  As[seg + 3][r] = a.w;
            Bs[seg + 0][r] = bb.x; Bs[seg + 1][r] = bb.y;
            Bs[seg + 2][r] = bb.z; Bs[seg + 3][r] = bb.w;
            __syncthreads();
            #pragma unroll
            for (int kk = 0; kk < 8; kk++) {
                float av[8], bv[8];
                *(float4*)(av)     = *(const float4*)&As[kk][ty * 8];
                *(float4*)(av + 4) = *(const float4*)&As[kk][ty * 8 + 4];
                *(float4*)(bv)     = *(const float4*)&Bs[kk][tx * 8];
                *(float4*)(bv + 4) = *(const float4*)&Bs[kk][tx * 8 + 4];
                #pragma unroll
                for (int i = 0; i < 8; i++)
                    #pragma unroll
                    for (int j = 0; j < 8; j++)
                        acc[i][j] = fmaf(av[i], bv[j], acc[i][j]);
            }
        }
        #pragma unroll
        for (int i = 0; i < 8; i++)
            #pragma unroll
            for (int j = 0; j < 8; j++)
                rowsum[i] += __expf(acc[i][j]);
    }

    #pragma unroll
    for (int i = 0; i < 8; i++) sred[ty * 8 + i][tx] = rowsum[i];
    __syncthreads();
    if (tid < 128) {
        float s = 0.f;
        #pragma unroll
        for (int t = 0; t < 16; t++) s += sred[tid][t];
        g_upart[((size_t)blockIdx.x * BATCH + b) * NPIX + nBase + tid] = s;
    }
#endif
}

__global__ __launch_bounds__(256)
void vsum_f()
{
#if !TC_OK
    __shared__ float As[8][128];
    __shared__ float Bs[8][128];
    __shared__ float sred[128][17];

    const int b       = blockIdx.z;
    const int mBase   = blockIdx.y * 128;
    const int nRegion = blockIdx.x * (NPIX / MSPLIT);
    const int tid = threadIdx.x;
    const int r   = tid >> 1;
    const int seg = (tid & 1) * 4;
    const int tx  = tid & 15;
    const int ty  = tid >> 4;

    const __nv_bfloat16* qh = g_qh + (size_t)b * NPIX * DIM;
    const __nv_bfloat16* ql = g_ql + (size_t)b * NPIX * DIM;
    const __nv_bfloat16* kh = g_kh + (size_t)b * NPIX * DIM;
    const __nv_bfloat16* kl = g_kl + (size_t)b * NPIX * DIM;
    const float* ub = g_u + b * NPIX;

    float colsum[8];
    #pragma unroll
    for (int j = 0; j < 8; j++) colsum[j] = 0.f;

    for (int nt = 0; nt < (NPIX / MSPLIT) / 128; nt++) {
        const int nBase = nRegion + nt * 128;
        float acc[8][8];
        #pragma unroll
        for (int i = 0; i < 8; i++)
            #pragma unroll
            for (int j = 0; j < 8; j++) acc[i][j] = 0.f;

        for (int k0 = 0; k0 < DIM; k0 += 8) {
            float4 a  = ld_split4(qh, ql, (size_t)(nBase + r) * DIM + k0 + seg);
            float4 bb = ld_split4(kh, kl, (size_t)(mBase + r) * DIM + k0 + seg);
            __syncthreads();
            As[seg + 0][r] = a.x;  As[seg + 1][r] = a.y;
            As[seg + 2][r] = a.z;  As[seg + 3][r] = a.w;
            Bs[seg + 0][r] = bb.x; Bs[seg + 1][r] = bb.y;
            Bs[seg + 2][r] = bb.z; Bs[seg + 3][r] = bb.w;
            __syncthreads();
            #pragma unroll
            for (int kk = 0; kk < 8; kk++) {
                float av[8], bv[8];
                *(float4*)(av)     = *(const float4*)&As[kk][ty * 8];
                *(float4*)(av + 4) = *(const float4*)&As[kk][ty * 8 + 4];
                *(float4*)(bv)     = *(const float4*)&Bs[kk][tx * 8];
                *(float4*)(bv + 4) = *(const float4*)&Bs[kk][tx * 8 + 4];
                #pragma unroll
                for (int i = 0; i < 8; i++)
                    #pragma unroll
                    for (int j = 0; j < 8; j++)
                        acc[i][j] = fmaf(av[i], bv[j], acc[i][j]);
            }
        }
        float uval[8];
        #pragma unroll
        for (int i = 0; i < 8; i++) uval[i] = ub[nBase + ty * 8 + i];
        #pragma unroll
        for (int i = 0; i < 8; i++)
            #pragma unroll
            for (int j = 0; j < 8; j++)
                colsum[j] += __expf(acc[i][j] + uval[i]);
    }

    #pragma unroll
    for (int j = 0; j < 8; j++) sred[tx * 8 + j][ty] = colsum[j];
    __syncthreads();
    if (tid < 128) {
        float s = 0.f;
        #pragma unroll
        for (int t = 0; t < 16; t++) s += sred[tid][t];
        g_vpart[((size_t)blockIdx.x * BATCH + b) * NPIX + mBase + tid] = s;
    }
#endif
}

__global__ __launch_bounds__(256, 1)
void out_f(float* __restrict__ out)
{
#if !TC_OK
    __shared__ float Ps[64][128];
    __shared__ __align__(16) char shbuf[16 * 256 * 4];
    float (*Qs)[64]  = (float(*)[64])shbuf;
    float (*Ks)[128] = (float(*)[128])(shbuf + 8 * 64 * 4);
    float4 (*Vs)[64] = (float4(*)[64])shbuf;

    const int b     = blockIdx.y;
    const int nBase = blockIdx.x * 64;
    const int tid   = threadIdx.x;
    const int tx    = tid & 15;
    const int ty    = tid >> 4;

    const __nv_bfloat16* qh = g_qh + (size_t)b * NPIX * DIM;
    const __nv_bfloat16* ql = g_ql + (size_t)b * NPIX * DIM;
    const __nv_bfloat16* kh = g_kh + (size_t)b * NPIX * DIM;
    const __nv_bfloat16* kl = g_kl + (size_t)b * NPIX * DIM;
    const float* vb  = g_v  + (size_t)b * NPIX * DIM;
    const float* vpb = g_vp + b * NPIX;

    float acc2[4][16];
    #pragma unroll
    for (int i = 0; i < 4; i++)
        #pragma unroll
        for (int j = 0; j < 16; j++) acc2[i][j] = 0.f;

    for (int mt = 0; mt < NPIX / 128; mt++) {
        const int mBase = mt * 128;

        float Sacc[4][8];
        #pragma unroll
        for (int i = 0; i < 4; i++)
            #pragma unroll
            for (int j = 0; j < 8; j++) Sacc[i][j] = 0.f;

        for (int k0 = 0; k0 < DIM; k0 += 8) {
            float4 qv, kv;
            const int lr = tid >> 1, lseg = (tid & 1) * 4;
            if (tid < 128)
                qv = ld_split4(qh, ql, (size_t)(nBase + lr) * DIM + k0 + lseg);
            kv = ld_split4(kh, kl, (size_t)(mBase + lr) * DIM + k0 + lseg);
            __syncthreads();
            if (tid < 128) {
                Qs[lseg + 0][lr] = qv.x; Qs[lseg + 1][lr] = qv.y;
                Qs[lseg + 2][lr] = qv.z; Qs[lseg + 3][lr] = qv.w;
            }
            Ks[lseg + 0][lr] = kv.x; Ks[lseg + 1][lr] = kv.y;
            Ks[lseg + 2][lr] = kv.z; Ks[lseg + 3][lr] = kv.w;
            __syncthreads();
            #pragma unroll
            for (int kk = 0; kk < 8; kk++) {
                float av[4], bv[8];
                *(float4*)av       = *(const float4*)&Qs[kk][ty * 4];
                *(float4*)(bv)     = *(const float4*)&Ks[kk][tx * 8];
                *(float4*)(bv + 4) = *(const float4*)&Ks[kk][tx * 8 + 4];
                #pragma unroll
                for (int i = 0; i < 4; i++)
                    #pragma unroll
                    for (int j = 0; j < 8; j++)
                        Sacc[i][j] = fmaf(av[i], bv[j], Sacc[i][j]);
            }
        }

        float vpv[8];
        #pragma unroll
        for (int j = 0; j < 8; j++) vpv[j] = vpb[mBase + tx * 8 + j];
        #pragma unroll
        for (int i = 0; i < 4; i++) {
            float4 p0, p1;
            p0.x = __expf(Sacc[i][0] + vpv[0]);
            p0.y = __expf(Sacc[i][1] + vpv[1]);
            p0.z = __expf(Sacc[i][2] + vpv[2]);
            p0.w = __expf(Sacc[i][3] + vpv[3]);
            p1.x = __expf(Sacc[i][4] + vpv[4]);
            p1.y = __expf(Sacc[i][5] + vpv[5]);
            p1.z = __expf(Sacc[i][6] + vpv[6]);
            p1.w = __expf(Sacc[i][7] + vpv[7]);
            *(float4*)&Ps[ty * 4 + i][tx * 8]     = p0;
            *(float4*)&Ps[ty * 4 + i][tx * 8 + 4] = p1;
        }

        for (int sub = 0; sub < 8; sub++) {
            const int mrow = tid >> 4;
            float4 vl[4];
            #pragma unroll
            for (int c4 = 0; c4 < 4; c4++)
                vl[c4] = *(const float4*)(vb + (size_t)(mBase + sub * 16 + mrow) * DIM
                                          + tx * 16 + c4 * 4);
            __syncthreads();
            #pragma unroll
            for (int c4 = 0; c4 < 4; c4++) Vs[mrow][tx * 4 + c4] = vl[c4];
            __syncthreads();
            #pragma unroll
            for (int kk = 0; kk < 16; kk++) {
                const int kg = (sub << 4) + kk;
                float av[4];
                #pragma unroll
                for (int i = 0; i < 4; i++) av[i] = Ps[ty * 4 + i][kg];
                #pragma unroll
                for (int jd4 = 0; jd4 < 4; jd4++) {
                    float4 v4 = Vs[kk][jd4 * 16 + tx];
                    #pragma unroll
                    for (int i = 0; i < 4; i++) {
                        acc2[i][jd4 * 4 + 0] = fmaf(av[i], v4.x, acc2[i][jd4 * 4 + 0]);
                        acc2[i][jd4 * 4 + 1] = fmaf(av[i], v4.y, acc2[i][jd4 * 4 + 1]);
                        acc2[i][jd4 * 4 + 2] = fmaf(av[i], v4.z, acc2[i][jd4 * 4 + 2]);
                        acc2[i][jd4 * 4 + 3] = fmaf(av[i], v4.w, acc2[i][jd4 * 4 + 3]);
                    }
                }
            }
        }
    }

    float eu[4];
    #pragma unroll
    for (int i = 0; i < 4; i++)
        eu[i] = __expf(g_u[b * NPIX + nBase + ty * 4 + i]);

    #pragma unroll
    for (int jd4 = 0; jd4 < 4; jd4++) {
        #pragma unroll
        for (int c = 0; c < 4; c++) {
            const int d = jd4 * 64 + tx * 4 + c;
            float4 o;
            o.x = eu[0] * acc2[0][jd4 * 4 + c];
            o.y = eu[1] * acc2[1][jd4 * 4 + c];
            o.z = eu[2] * acc2[2][jd4 * 4 + c];
            o.w = eu[3] * acc2[3][jd4 * 4 + c];
            *(float4*)(out + ((size_t)b * DIM + d) * NPIX + nBase + ty * 4) = o;
        }
    }
#else
    (void)out;
#endif
}

// ================================================================
// Shared combine kernels (always run)
// ================================================================
__global__ __launch_bounds__(256)
void ucomb_kernel()
{
    const int idx = blockIdx.x * 256 + threadIdx.x;
    float s = 0.f;
    #pragma unroll
    for (int r = 0; r < MSPLIT; r++) s += g_upart[(size_t)r * BATCH * NPIX + idx];
    const float logm = logf(1.0f / (float)NPIX + 1e-8f);
    g_u[idx] = logm - logf(s);
}

__global__ __launch_bounds__(256)
void vcomb_kernel()
{
    const int idx = blockIdx.x * 256 + threadIdx.x;
    float s = 0.f;
    #pragma unroll
    for (int r = 0; r < MSPLIT; r++) s += g_vpart[(size_t)r * BATCH * NPIX + idx];
    const float logm = logf(1.0f / (float)NPIX + 1e-8f);
    g_vp[idx] = logm - logf(s);
}

// ================================================================
extern "C" void kernel_launch(void* const* d_in, const int* in_sizes, int n_in,
                              void* d_out, int out_size)
{
    const float* x    = (const float*)d_in[0];
    const float* Wm   = (const float*)d_in[1];
    const float* bias = (const float*)d_in[2];
    float* out = (float*)d_out;
    (void)in_sizes; (void)n_in; (void)out_size;

    cudaFuncSetAttribute(usum_t, cudaFuncAttributeMaxDynamicSharedMemorySize, SMEM_SUM);
    cudaFuncSetAttribute(vsum_t, cudaFuncAttributeMaxDynamicSharedMemorySize, SMEM_SUM);
    cudaFuncSetAttribute(out_t,  cudaFuncAttributeMaxDynamicSharedMemorySize, SMEM_OUT);

    {   // 1) QKV projection (writes all operand formats)
        dim3 g(NPIX / 64, OCH / 64, BATCH);
        qkv_kernel<<<g, 256>>>(x, Wm, bias);
    }
    {   // 2) row sums — tensor variant + FFMA variant (one is a stub)
        dim3 g(MSPLIT, NPIX / 128, BATCH);
        usum_t<<<g, NT, SMEM_SUM>>>();
        usum_f<<<g, 256>>>();
    }
    {   // 3) u
        ucomb_kernel<<<(BATCH * NPIX) / 256, 256>>>();
    }
    {   // 4) col sums
        dim3 g(MSPLIT, NPIX / 128, BATCH);
        vsum_t<<<g, NT, SMEM_SUM>>>();
        vsum_f<<<g, 256>>>();
    }
    {   // 5) vp
        vcomb_kernel<<<(BATCH * NPIX) / 256, 256>>>();
    }
    {   // 6) out
        dim3 gt(NPIX / 128, BATCH);
        out_t<<<gt, NT, SMEM_OUT>>>(out);
        dim3 gf(NPIX / 64, BATCH);
        out_f<<<gf, 256>>>(out);
    }
}